// round 1
// baseline (speedup 1.0000x reference)
#include <cuda_runtime.h>
#include <cuda_bf16.h>

#define N_NODES 50000
#define N_EDGES 800000
#define D       64
#define ROWS    128   // rows per block in the dense kernel

// Scratch: neighbor aggregation buffer (no cudaMalloc allowed)
__device__ float g_neigh[N_NODES * D];

// ---------------------------------------------------------------------------
// Kernel 1: zero the aggregation buffer (vectorized)
// ---------------------------------------------------------------------------
__global__ void zero_kernel() {
    int i = blockIdx.x * blockDim.x + threadIdx.x;
    float4* p = reinterpret_cast<float4*>(g_neigh);
    if (i < (N_NODES * D) / 4) p[i] = make_float4(0.f, 0.f, 0.f, 0.f);
}

// ---------------------------------------------------------------------------
// Kernel 2: scatter  g_neigh[dst] += w * h[src]
// 16 threads per edge, each handles one float4 (lane*4 .. lane*4+3).
// Vector RED (red.global.add.v4.f32, sm_90+) cuts atomic op count 4x.
// ---------------------------------------------------------------------------
__global__ void scatter_kernel(const float* __restrict__ h,
                               const int*   __restrict__ src,
                               const int*   __restrict__ dst,
                               const float* __restrict__ w) {
    int t = blockIdx.x * blockDim.x + threadIdx.x;
    int e    = t >> 4;
    int lane = t & 15;
    if (e >= N_EDGES) return;

    int   s  = __ldg(src + e);
    int   d  = __ldg(dst + e);
    float wt = __ldg(w + e);

    const float4 v = *reinterpret_cast<const float4*>(h + (size_t)s * D + lane * 4);
    float a = v.x * wt, b = v.y * wt, c = v.z * wt, dd = v.w * wt;

    float* p = g_neigh + (size_t)d * D + lane * 4;
    asm volatile("red.global.add.v4.f32 [%0], {%1, %2, %3, %4};"
                 :: "l"(p), "f"(a), "f"(b), "f"(c), "f"(dd)
                 : "memory");
}

// ---------------------------------------------------------------------------
// Kernel 3: dense  out = relu([h | neigh] @ [W_self | W_neigh]^T + b_self + b_neigh)
// One thread per output row; 64 fp32 accumulators in registers.
// Combined transposed weight (sW[k][j], k=0..127) in smem, read as broadcast
// LDS.128 (1 shared load feeds 4 FFMAs across all lanes).
// x staged in smem chunks of 32 k-values with stride-129 padding so the
// coalesced-global-load -> transposed-smem-write is bank-conflict-free.
// ---------------------------------------------------------------------------
__global__ __launch_bounds__(ROWS)
void dense_kernel(const float* __restrict__ h,
                  const float* __restrict__ Ws, const float* __restrict__ bs,
                  const float* __restrict__ Wn, const float* __restrict__ bn,
                  float* __restrict__ out) {
    __shared__ float sW[128 * 64];        // sW[k*64 + j]; k<64 -> W_self, k>=64 -> W_neigh
    __shared__ float sX[32][ROWS + 1];    // stride 129 floats: conflict-free both ways
    __shared__ float sB[64];

    const int tid     = threadIdx.x;
    const int rowBase = blockIdx.x * ROWS;
    const int row     = rowBase + tid;
    const bool valid  = row < N_NODES;

    // Load combined W^T: sW[k][j] = W[j][k]
    for (int idx = tid; idx < 128 * 64; idx += ROWS) {
        int k = idx >> 6, j = idx & 63;
        sW[idx] = (k < 64) ? Ws[j * 64 + k] : Wn[j * 64 + (k - 64)];
    }
    if (tid < 64) sB[tid] = bs[tid] + bn[tid];

    float acc[64];
#pragma unroll
    for (int j = 0; j < 64; j++) acc[j] = 0.f;

    const int lane = tid & 31;   // k offset within chunk (coalesced load dim)
    const int rq   = tid >> 5;   // row phase

    for (int kc = 0; kc < 4; kc++) {
        const float* srcp = (kc < 2) ? h : g_neigh;
        const int colBase = (kc & 1) * 32;

        __syncthreads();  // protect sX reuse (also covers sW/sB on first iter)

        // Stage: sX[k][r] = x[rowBase + r][kc*32 + k], coalesced global reads
        for (int r = rq; r < ROWS; r += ROWS / 32) {
            int rr = rowBase + r;
            float val = (rr < N_NODES) ? srcp[(size_t)rr * D + colBase + lane] : 0.f;
            sX[lane][r] = val;
        }
        __syncthreads();

        const float4* sW4 = reinterpret_cast<const float4*>(sW) + kc * 32 * 16;
#pragma unroll
        for (int kk = 0; kk < 32; kk++) {
            float x = sX[kk][tid];
            const float4* wrow = sW4 + kk * 16;
#pragma unroll
            for (int j4 = 0; j4 < 16; j4++) {
                float4 wv = wrow[j4];     // broadcast LDS.128
                acc[4 * j4 + 0] = fmaf(x, wv.x, acc[4 * j4 + 0]);
                acc[4 * j4 + 1] = fmaf(x, wv.y, acc[4 * j4 + 1]);
                acc[4 * j4 + 2] = fmaf(x, wv.z, acc[4 * j4 + 2]);
                acc[4 * j4 + 3] = fmaf(x, wv.w, acc[4 * j4 + 3]);
            }
        }
    }

    if (valid) {
        float4* op = reinterpret_cast<float4*>(out + (size_t)row * D);
#pragma unroll
        for (int j4 = 0; j4 < 16; j4++) {
            float4 o;
            o.x = fmaxf(acc[4 * j4 + 0] + sB[4 * j4 + 0], 0.f);
            o.y = fmaxf(acc[4 * j4 + 1] + sB[4 * j4 + 1], 0.f);
            o.z = fmaxf(acc[4 * j4 + 2] + sB[4 * j4 + 2], 0.f);
            o.w = fmaxf(acc[4 * j4 + 3] + sB[4 * j4 + 3], 0.f);
            op[j4] = o;
        }
    }
}

// ---------------------------------------------------------------------------
// kernel_launch: inputs per reference order
//   0: h [N,D] f32   1: edge_src [E] i32   2: edge_dst [E] i32   3: edge_w [E] f32
//   4: W_self [D,D]  5: b_self [D]         6: W_neigh [D,D]      7: b_neigh [D]
// ---------------------------------------------------------------------------
extern "C" void kernel_launch(void* const* d_in, const int* in_sizes, int n_in,
                              void* d_out, int out_size) {
    const float* h        = (const float*)d_in[0];
    const int*   edge_src = (const int*)  d_in[1];
    const int*   edge_dst = (const int*)  d_in[2];
    const float* edge_w   = (const float*)d_in[3];
    const float* W_self   = (const float*)d_in[4];
    const float* b_self   = (const float*)d_in[5];
    const float* W_neigh  = (const float*)d_in[6];
    const float* b_neigh  = (const float*)d_in[7];
    float* out = (float*)d_out;

    // 1) zero aggregation buffer
    {
        int n4 = (N_NODES * D) / 4;
        zero_kernel<<<(n4 + 255) / 256, 256>>>();
    }

    // 2) scatter: 16 threads/edge
    {
        long long total = (long long)N_EDGES * 16;
        int threads = 256;
        int blocks = (int)((total + threads - 1) / threads);
        scatter_kernel<<<blocks, threads>>>(h, edge_src, edge_dst, edge_w);
    }

    // 3) fused dense + bias + relu
    {
        int blocks = (N_NODES + ROWS - 1) / ROWS;
        dense_kernel<<<blocks, ROWS>>>(h, W_self, b_self, W_neigh, b_neigh, out);
    }
}